// round 15
// baseline (speedup 1.0000x reference)
#include <cuda_runtime.h>
#include <math_constants.h>

#define BATCH    8192
#define OBSD     32
#define HDIM     256
#define CDIM     16
#define NCODE    512
#define ROWS     (BATCH * OBSD)

#define DTR      32
#define DTHREADS 256
#define KC       32

__device__ float g_q[(size_t)ROWS * CDIM];
__device__ float g_e[(size_t)ROWS * CDIM];
__device__ float g_t[OBSD * HDIM];
__device__ float g_tab[(size_t)OBSD * (HDIM + 1) * (2 * HDIM)];

typedef unsigned long long u64;
__device__ __forceinline__ u64 f2pack(float lo, float hi) {
    u64 r; asm("mov.b64 %0, {%1, %2};" : "=l"(r) : "f"(lo), "f"(hi)); return r;
}
__device__ __forceinline__ u64 ffma2(u64 a, u64 b, u64 c) {
    u64 d; asm("fma.rn.f32x2 %0, %1, %2, %3;" : "=l"(d) : "l"(a), "l"(b), "l"(c)); return d;
}
__device__ __forceinline__ u64 fmul2(u64 a, u64 b) {
    u64 d; asm("mul.rn.f32x2 %0, %1, %2;" : "=l"(d) : "l"(a), "l"(b)); return d;
}
__device__ __forceinline__ u64 fadd2(u64 a, u64 b) {
    u64 d; asm("add.rn.f32x2 %0, %1, %2;" : "=l"(d) : "l"(a), "l"(b)); return d;
}
__device__ __forceinline__ float f2lo(u64 v) { return __uint_as_float((unsigned)v); }
__device__ __forceinline__ float f2hi(u64 v) { return __uint_as_float((unsigned)(v >> 32)); }
__device__ __forceinline__ u64 shfl_xor_u64(u64 v, int off) {
    unsigned lo = __shfl_xor_sync(0xffffffffu, (unsigned)v, off);
    unsigned hi = __shfl_xor_sync(0xffffffffu, (unsigned)(v >> 32), off);
    return ((u64)hi << 32) | lo;
}
__device__ __forceinline__ void kadd(float& s, float& c, float y) {
    float t = s + y;
    c += (fabsf(s) >= fabsf(y)) ? ((s - t) + y) : ((y - t) + s);
    s = t;
}

// ============ PWL builder (unchanged) ============
#define P_ST   0
#define P_SW   256
#define P_SC   512
#define P_ORD  768
#define P_ACT  1024
#define P_W1S  1280
#define P_SMEM_FLOATS (1280 + 256 * 64)
#define P_SMEM_BYTES  (P_SMEM_FLOATS * 4)

__global__ __launch_bounds__(256, 1)
void pwl_build_kernel(const float* __restrict__ W0,
                      const float* __restrict__ b0,
                      const float* __restrict__ W1,
                      const float* __restrict__ b1)
{
    extern __shared__ float ps[];
    int*  pord = (int*)(ps + P_ORD);
    int*  pact = (int*)(ps + P_ACT);
    const int d  = blockIdx.x >> 2;
    const int jq = blockIdx.x & 3;
    const int t  = threadIdx.x;

    {
        float w = W0[t];
        float c = W0[(1 + d) * HDIM + t] + b0[t];
        int act; float tv;
        if (w > 0.f)      { act = 1; tv = -c / w; }
        else if (w < 0.f) { act = 0; tv = -c / w; }
        else              { act = (c <= 0.f) ? 1 : 0; tv = CUDART_INF_F; }
        ps[P_ST + t] = tv; ps[P_SW + t] = w; ps[P_SC + t] = c; pact[t] = act;
    }
    {
        const float4* src = (const float4*)(W1 + t * HDIM + jq * 64);
        float4* dst = (float4*)(ps + P_W1S + t * 64);
        #pragma unroll
        for (int i = 0; i < 16; i++) dst[i] = src[i];
    }
    __syncthreads();
    {
        float tv = ps[P_ST + t];
        int rank = 0;
        for (int k2 = 0; k2 < HDIM; k2++) {
            float t2 = ps[P_ST + k2];
            rank += (t2 < tv || (t2 == tv && k2 < t)) ? 1 : 0;
        }
        pord[rank] = t;
        if (jq == 0) g_t[d * HDIM + rank] = tv;
    }
    __syncthreads();

    if (t < 64) {
        const int j = jq * 64 + t;
        float As = 0.f, Ac = 0.f, Bs = 0.f, Bc = 0.f;
        for (int kk = 0; kk < HDIM; kk++) {
            if (!pact[kk]) {
                float w1v = ps[P_W1S + kk * 64 + t];
                kadd(As, Ac, ps[P_SW + kk] * w1v);
                kadd(Bs, Bc, ps[P_SC + kk] * w1v);
            }
        }
        const float bj = b1[j];
        float* tab = g_tab + (size_t)d * (HDIM + 1) * (2 * HDIM);
        tab[j] = As + Ac;
        tab[HDIM + j] = Bs + Bc + bj;
        for (int s = 1; s <= HDIM; s++) {
            int kk = pord[s - 1];
            float w1v = ps[P_W1S + kk * 64 + t];
            float sgn = pact[kk] ? 1.f : -1.f;
            kadd(As, Ac, sgn * ps[P_SW + kk] * w1v);
            kadd(Bs, Bc, sgn * ps[P_SC + kk] * w1v);
            tab[(size_t)s * (2 * HDIM) + j] = As + Ac;
            tab[(size_t)s * (2 * HDIM) + HDIM + j] = Bs + Bc + bj;
        }
    }
}

// ============ E1: PWL h1 + emb -> g_e (R12 version, unchanged) ============
#define E1_W2   0
#define E1_T    4096
#define E1_OB   12288
#define E1_SMEM_FLOATS 12416
#define E1_SMEM_BYTES  (E1_SMEM_FLOATS * 4)

__global__ __launch_bounds__(512, 2)
void enc_emb_kernel(const float* __restrict__ obs,
                    const float* __restrict__ W2,
                    const float* __restrict__ b2)
{
    extern __shared__ float sm[];
    const int tid  = threadIdx.x;
    const int base = blockIdx.x * 128;

    if (tid < 128) sm[E1_OB + tid] = obs[base + tid];
    for (int idx = tid; idx < HDIM * CDIM; idx += 512) {
        int c = idx >> 4, jf = idx & 15;
        int lp = jf >> 2;
        int pp = (lp + (c >> 6)) & 3;
        sm[E1_W2 + c * 16 + pp * 4 + (jf & 3)] = W2[idx];
    }
    for (int i = tid; i < OBSD * HDIM; i += 512) sm[E1_T + i] = g_t[i];
    __syncthreads();

    const int r = tid >> 2, q = tid & 3;
    const int d = (base + r) & (OBSD - 1);
    const float x = sm[E1_OB + r];
    const float* td = sm + E1_T + d * HDIM;
    int seg;
    if (td[HDIM - 1] < x) seg = HDIM;
    else {
        seg = 0;
        #pragma unroll
        for (int w = HDIM / 2; w >= 1; w >>= 1)
            if (td[seg + w - 1] < x) seg += w;
    }
    const float* tab = g_tab + (size_t)(d * (HDIM + 1) + seg) * (2 * HDIM);

    u64 e2[8];
    if (q == 0) {
        const u64* bp = (const u64*)b2;
        #pragma unroll
        for (int k = 0; k < 8; k++) e2[k] = bp[k];
    } else {
        #pragma unroll
        for (int k = 0; k < 8; k++) e2[k] = 0ull;
    }
    const float4* Ap = (const float4*)(tab + q * 64);
    const float4* Bp = (const float4*)(tab + HDIM + q * 64);
    #pragma unroll 4
    for (int i4 = 0; i4 < 16; i4++) {
        float4 a = Ap[i4];
        float4 b = Bp[i4];
        float hv[4];
        hv[0] = fmaxf(fmaf(a.x, x, b.x), 0.f);
        hv[1] = fmaxf(fmaf(a.y, x, b.y), 0.f);
        hv[2] = fmaxf(fmaf(a.z, x, b.z), 0.f);
        hv[3] = fmaxf(fmaf(a.w, x, b.w), 0.f);
        #pragma unroll
        for (int m = 0; m < 4; m++) {
            int c = q * 64 + i4 * 4 + m;
            u64 h2 = f2pack(hv[m], hv[m]);
            const float* wrow = sm + E1_W2 + c * 16;
            #pragma unroll
            for (int lp = 0; lp < 4; lp++) {
                ulonglong2 w = *(const ulonglong2*)(wrow + ((lp + q) & 3) * 4);
                e2[2 * lp]     = ffma2(h2, w.x, e2[2 * lp]);
                e2[2 * lp + 1] = ffma2(h2, w.y, e2[2 * lp + 1]);
            }
        }
    }
    #pragma unroll
    for (int off = 1; off < 4; off <<= 1)
        #pragma unroll
        for (int k = 0; k < 8; k++)
            e2[k] = fadd2(e2[k], shfl_xor_u64(e2[k], off));
    if (q == 0) {
        ulonglong2* ep = (ulonglong2*)&g_e[(size_t)(base + r) * CDIM];
        ep[0] = make_ulonglong2(e2[0], e2[1]);
        ep[1] = make_ulonglong2(e2[2], e2[3]);
        ep[2] = make_ulonglong2(e2[4], e2[5]);
        ep[3] = make_ulonglong2(e2[6], e2[7]);
    }
}

// ============ E2 v2: codes in REGISTERS, e broadcast, redux argmin ============
// warp w owns codes [64w, 64w+64); lane l holds codes 64w+2l, 64w+2l+1 in regs.
__global__ __launch_bounds__(256, 3)
void enc_dist_kernel(const float* __restrict__ cb)
{
    __shared__ float se[64 * 16];       // e tile
    __shared__ u64   part[64][8];       // per-warp (key<<32 | idx)
    __shared__ int   jb[64];
    const int tid = threadIdx.x;
    const int w = tid >> 5, l = tid & 31;
    const int base = blockIdx.x * 64;

    // load 2 codes (128B contiguous per lane -> fully coalesced per warp)
    u64 cr[2][8];
    float cn[2];
    const int j0 = w * 64 + l * 2;
    {
        const ulonglong2* cp = (const ulonglong2*)(cb + (size_t)j0 * CDIM);
        #pragma unroll
        for (int m = 0; m < 2; m++) {
            #pragma unroll
            for (int i = 0; i < 4; i++) {
                ulonglong2 v = cp[m * 4 + i];
                cr[m][i * 2]     = v.x;
                cr[m][i * 2 + 1] = v.y;
            }
            float s = 0.f;
            #pragma unroll
            for (int k = 0; k < 8; k++) {
                float a = f2lo(cr[m][k]), b = f2hi(cr[m][k]);
                s = fmaf(a, a, s);
                s = fmaf(b, b, s);
            }
            cn[m] = s;
        }
    }
    // stage e tile (coalesced)
    {
        int r = tid >> 2, q4 = tid & 3;
        float4 v = *(const float4*)&g_e[(size_t)(base + r) * CDIM + q4 * 4];
        *(float4*)&se[r * 16 + q4 * 4] = v;
    }
    __syncthreads();

    #pragma unroll 2
    for (int r = 0; r < 64; r++) {
        u64 er[8];
        {   // broadcast reads (all lanes same address -> conflict-free)
            const ulonglong2* ep = (const ulonglong2*)(se + r * 16);
            #pragma unroll
            for (int i = 0; i < 4; i++) {
                ulonglong2 v = ep[i];
                er[i * 2] = v.x; er[i * 2 + 1] = v.y;
            }
        }
        float best = CUDART_INF_F; int bi = NCODE;
        #pragma unroll
        for (int m = 0; m < 2; m++) {
            u64 p0 = fmul2(er[0], cr[m][0]);
            u64 p1 = fmul2(er[1], cr[m][1]);
            p0 = ffma2(er[2], cr[m][2], p0);
            p1 = ffma2(er[3], cr[m][3], p1);
            p0 = ffma2(er[4], cr[m][4], p0);
            p1 = ffma2(er[5], cr[m][5], p1);
            p0 = ffma2(er[6], cr[m][6], p0);
            p1 = ffma2(er[7], cr[m][7], p1);
            u64 pz = fadd2(p0, p1);
            float dot = f2lo(pz) + f2hi(pz);
            float dist = fmaf(-2.f, dot, cn[m]);
            if (dist < best) { best = dist; bi = j0 + m; }
        }
        // order-preserving float->uint key (bijective, exact)
        unsigned u = __float_as_uint(best);
        unsigned key = u ^ (unsigned)(((int)u >> 31) | 0x80000000);
        unsigned kmin;
        asm("redux.sync.min.u32 %0, %1, 0xffffffff;" : "=r"(kmin) : "r"(key));
        unsigned mk = __ballot_sync(0xffffffffu, key == kmin);
        int src = __ffs(mk) - 1;               // lowest lane = smallest idx
        int jwin = __shfl_sync(0xffffffffu, bi, src);
        if (l == 0) part[r][w] = ((u64)kmin << 32) | (unsigned)jwin;
    }
    __syncthreads();
    if (tid < 64) {
        u64 m = part[tid][0];
        #pragma unroll
        for (int i = 1; i < 8; i++) { u64 p = part[tid][i]; m = (p < m) ? p : m; }
        jb[tid] = (int)(unsigned)m;
    }
    __syncthreads();
    {
        int r = tid >> 2, q4 = tid & 3;
        int j = jb[r];
        float4 v = *(const float4*)&cb[(size_t)j * CDIM + q4 * 4];
        *(float4*)&g_q[(size_t)(base + r) * CDIM + q4 * 4] = v;
    }
}

// ---------------- decoder (R12/R9 version, unchanged) ----------------
#define D_ST    0
#define D_SA    9216
#define D_SB    10368
#define D_SMEM_FLOATS 18560
#define D_SMEM_BYTES  (D_SMEM_FLOATS * 4)

__global__ __launch_bounds__(DTHREADS, 2)
void dec_kernel(const float* __restrict__ W0,
                const float* __restrict__ b0,
                const float* __restrict__ W1,
                const float* __restrict__ b1,
                const float* __restrict__ W2,
                const float* __restrict__ b2,
                float* __restrict__ out)
{
    extern __shared__ float sm[];
    const int tid  = threadIdx.x;
    const int base = blockIdx.x * DTR;
    const int cg   = tid & 31;
    const int rg   = tid >> 5;

    float acc[4][8];
    #pragma unroll
    for (int i = 0; i < 4; i++)
        #pragma unroll
        for (int j = 0; j < 8; j++) acc[i][j] = 0.f;

    for (int k0 = 0; k0 < 2 * HDIM; k0 += KC) {
        __syncthreads();
        {
            int r   = tid >> 3;
            int kk0 = (tid & 7) << 2;
            const float* src = g_q + (size_t)(base + r) * (2 * HDIM) + k0 + kk0;
            float4 v = *(const float4*)src;
            sm[D_SA + (kk0 + 0) * 36 + r] = v.x;
            sm[D_SA + (kk0 + 1) * 36 + r] = v.y;
            sm[D_SA + (kk0 + 2) * 36 + r] = v.z;
            sm[D_SA + (kk0 + 3) * 36 + r] = v.w;
        }
        {
            const float4* s = (const float4*)(W0 + k0 * HDIM);
            float4* d = (float4*)(sm + D_SB);
            #pragma unroll
            for (int i = 0; i < 8; i++) d[tid + i * DTHREADS] = s[tid + i * DTHREADS];
        }
        __syncthreads();
        #pragma unroll 8
        for (int kk = 0; kk < KC; kk++) {
            float4 av = *(const float4*)&sm[D_SA + kk * 36 + rg * 4];
            float a[4] = {av.x, av.y, av.z, av.w};
            float bb[8];
            #pragma unroll
            for (int i = 0; i < 8; i++) bb[i] = sm[D_SB + kk * HDIM + cg + 32 * i];
            #pragma unroll
            for (int ri = 0; ri < 4; ri++)
                #pragma unroll
                for (int ci = 0; ci < 8; ci++)
                    acc[ri][ci] = fmaf(a[ri], bb[ci], acc[ri][ci]);
        }
    }
    __syncthreads();
    {
        float bb[8];
        #pragma unroll
        for (int ci = 0; ci < 8; ci++) bb[ci] = b0[cg + 32 * ci];
        #pragma unroll
        for (int ci = 0; ci < 8; ci++) {
            int c = cg + 32 * ci;
            #pragma unroll
            for (int ri = 0; ri < 4; ri++)
                sm[D_ST + c * 36 + rg * 4 + ri] = fmaxf(acc[ri][ci] + bb[ci], 0.f);
        }
        #pragma unroll
        for (int i = 0; i < 4; i++)
            #pragma unroll
            for (int j = 0; j < 8; j++) acc[i][j] = 0.f;
    }

    for (int k0 = 0; k0 < HDIM; k0 += KC) {
        __syncthreads();
        {
            const float4* s = (const float4*)(W1 + k0 * HDIM);
            float4* d = (float4*)(sm + D_SB);
            #pragma unroll
            for (int i = 0; i < 8; i++) d[tid + i * DTHREADS] = s[tid + i * DTHREADS];
        }
        __syncthreads();
        #pragma unroll 8
        for (int kk = 0; kk < KC; kk++) {
            int k = k0 + kk;
            float4 av = *(const float4*)&sm[D_ST + k * 36 + rg * 4];
            float a[4] = {av.x, av.y, av.z, av.w};
            float bb[8];
            #pragma unroll
            for (int i = 0; i < 8; i++) bb[i] = sm[D_SB + kk * HDIM + cg + 32 * i];
            #pragma unroll
            for (int ri = 0; ri < 4; ri++)
                #pragma unroll
                for (int ci = 0; ci < 8; ci++)
                    acc[ri][ci] = fmaf(a[ri], bb[ci], acc[ri][ci]);
        }
    }
    __syncthreads();
    {
        float bb[8];
        #pragma unroll
        for (int ci = 0; ci < 8; ci++) bb[ci] = b1[cg + 32 * ci];
        #pragma unroll
        for (int ri = 0; ri < 4; ri++)
            #pragma unroll
            for (int ci = 0; ci < 8; ci++)
                sm[D_ST + (rg * 4 + ri) * 260 + cg + 32 * ci] =
                    fmaxf(acc[ri][ci] + bb[ci], 0.f);
        const float4* s = (const float4*)W2;
        float4* d = (float4*)(sm + D_SB);
        #pragma unroll
        for (int i = 0; i < 8; i++) d[tid + i * DTHREADS] = s[tid + i * DTHREADS];
    }
    __syncthreads();
    {
        int r = tid >> 3, part = tid & 7;
        int o0 = part * 4;
        float o[4];
        #pragma unroll
        for (int i = 0; i < 4; i++) o[i] = b2[o0 + i];
        #pragma unroll 4
        for (int c = 0; c < HDIM; c++) {
            float h = sm[D_ST + r * 260 + c];
            #pragma unroll
            for (int i = 0; i < 4; i++)
                o[i] = fmaf(h, sm[D_SB + c * OBSD + o0 + i], o[i]);
        }
        float4* dst = (float4*)&out[(size_t)(base + r) * OBSD + o0];
        *dst = make_float4(o[0], o[1], o[2], o[3]);
    }
}

// ======================= launcher =======================
extern "C" void kernel_launch(void* const* d_in, const int* in_sizes, int n_in,
                              void* d_out, int out_size) {
    (void)in_sizes; (void)n_in; (void)out_size;
    const float* obs = (const float*)d_in[0];
    const float* eW0 = (const float*)d_in[1];
    const float* eb0 = (const float*)d_in[2];
    const float* eW1 = (const float*)d_in[3];
    const float* eb1 = (const float*)d_in[4];
    const float* eW2 = (const float*)d_in[5];
    const float* eb2 = (const float*)d_in[6];
    const float* dW0 = (const float*)d_in[7];
    const float* db0 = (const float*)d_in[8];
    const float* dW1 = (const float*)d_in[9];
    const float* db1 = (const float*)d_in[10];
    const float* dW2 = (const float*)d_in[11];
    const float* db2 = (const float*)d_in[12];
    const float* cb  = (const float*)d_in[13];
    float* out = (float*)d_out;

    cudaFuncSetAttribute(pwl_build_kernel,
                         cudaFuncAttributeMaxDynamicSharedMemorySize, P_SMEM_BYTES);
    cudaFuncSetAttribute(enc_emb_kernel,
                         cudaFuncAttributeMaxDynamicSharedMemorySize, E1_SMEM_BYTES);
    cudaFuncSetAttribute(dec_kernel,
                         cudaFuncAttributeMaxDynamicSharedMemorySize, D_SMEM_BYTES);

    pwl_build_kernel<<<OBSD * 4, 256, P_SMEM_BYTES>>>(eW0, eb0, eW1, eb1);
    enc_emb_kernel<<<ROWS / 128, 512, E1_SMEM_BYTES>>>(obs, eW2, eb2);
    enc_dist_kernel<<<ROWS / 64, 256>>>(cb);
    dec_kernel<<<BATCH / DTR, DTHREADS, D_SMEM_BYTES>>>(
        dW0, db0, dW1, db1, dW2, db2, out);
}

// round 16
// speedup vs baseline: 1.5747x; 1.5747x over previous
#include <cuda_runtime.h>
#include <math_constants.h>

#define BATCH    8192
#define OBSD     32
#define HDIM     256
#define CDIM     16
#define NCODE    512
#define ROWS     (BATCH * OBSD)

#define DTR      32
#define DTHREADS 256
#define KC       32

__device__ float g_q[(size_t)ROWS * CDIM];
__device__ float g_e[(size_t)ROWS * CDIM];
__device__ float g_t[OBSD * HDIM];
__device__ float g_tab[(size_t)OBSD * (HDIM + 1) * (2 * HDIM)];

typedef unsigned long long u64;
__device__ __forceinline__ u64 f2pack(float lo, float hi) {
    u64 r; asm("mov.b64 %0, {%1, %2};" : "=l"(r) : "f"(lo), "f"(hi)); return r;
}
__device__ __forceinline__ u64 ffma2(u64 a, u64 b, u64 c) {
    u64 d; asm("fma.rn.f32x2 %0, %1, %2, %3;" : "=l"(d) : "l"(a), "l"(b), "l"(c)); return d;
}
__device__ __forceinline__ u64 fmul2(u64 a, u64 b) {
    u64 d; asm("mul.rn.f32x2 %0, %1, %2;" : "=l"(d) : "l"(a), "l"(b)); return d;
}
__device__ __forceinline__ u64 fadd2(u64 a, u64 b) {
    u64 d; asm("add.rn.f32x2 %0, %1, %2;" : "=l"(d) : "l"(a), "l"(b)); return d;
}
__device__ __forceinline__ float f2lo(u64 v) { return __uint_as_float((unsigned)v); }
__device__ __forceinline__ float f2hi(u64 v) { return __uint_as_float((unsigned)(v >> 32)); }
__device__ __forceinline__ u64 shfl_xor_u64(u64 v, int off) {
    unsigned lo = __shfl_xor_sync(0xffffffffu, (unsigned)v, off);
    unsigned hi = __shfl_xor_sync(0xffffffffu, (unsigned)(v >> 32), off);
    return ((u64)hi << 32) | lo;
}
__device__ __forceinline__ void kadd(float& s, float& c, float y) {
    float t = s + y;
    c += (fabsf(s) >= fabsf(y)) ? ((s - t) + y) : ((y - t) + s);
    s = t;
}

// ============ PWL builder (unchanged) ============
#define P_ST   0
#define P_SW   256
#define P_SC   512
#define P_ORD  768
#define P_ACT  1024
#define P_W1S  1280
#define P_SMEM_FLOATS (1280 + 256 * 64)
#define P_SMEM_BYTES  (P_SMEM_FLOATS * 4)

__global__ __launch_bounds__(256, 1)
void pwl_build_kernel(const float* __restrict__ W0,
                      const float* __restrict__ b0,
                      const float* __restrict__ W1,
                      const float* __restrict__ b1)
{
    extern __shared__ float ps[];
    int*  pord = (int*)(ps + P_ORD);
    int*  pact = (int*)(ps + P_ACT);
    const int d  = blockIdx.x >> 2;
    const int jq = blockIdx.x & 3;
    const int t  = threadIdx.x;

    {
        float w = W0[t];
        float c = W0[(1 + d) * HDIM + t] + b0[t];
        int act; float tv;
        if (w > 0.f)      { act = 1; tv = -c / w; }
        else if (w < 0.f) { act = 0; tv = -c / w; }
        else              { act = (c <= 0.f) ? 1 : 0; tv = CUDART_INF_F; }
        ps[P_ST + t] = tv; ps[P_SW + t] = w; ps[P_SC + t] = c; pact[t] = act;
    }
    {
        const float4* src = (const float4*)(W1 + t * HDIM + jq * 64);
        float4* dst = (float4*)(ps + P_W1S + t * 64);
        #pragma unroll
        for (int i = 0; i < 16; i++) dst[i] = src[i];
    }
    __syncthreads();
    {
        float tv = ps[P_ST + t];
        int rank = 0;
        for (int k2 = 0; k2 < HDIM; k2++) {
            float t2 = ps[P_ST + k2];
            rank += (t2 < tv || (t2 == tv && k2 < t)) ? 1 : 0;
        }
        pord[rank] = t;
        if (jq == 0) g_t[d * HDIM + rank] = tv;
    }
    __syncthreads();

    if (t < 64) {
        const int j = jq * 64 + t;
        float As = 0.f, Ac = 0.f, Bs = 0.f, Bc = 0.f;
        for (int kk = 0; kk < HDIM; kk++) {
            if (!pact[kk]) {
                float w1v = ps[P_W1S + kk * 64 + t];
                kadd(As, Ac, ps[P_SW + kk] * w1v);
                kadd(Bs, Bc, ps[P_SC + kk] * w1v);
            }
        }
        const float bj = b1[j];
        float* tab = g_tab + (size_t)d * (HDIM + 1) * (2 * HDIM);
        tab[j] = As + Ac;
        tab[HDIM + j] = Bs + Bc + bj;
        for (int s = 1; s <= HDIM; s++) {
            int kk = pord[s - 1];
            float w1v = ps[P_W1S + kk * 64 + t];
            float sgn = pact[kk] ? 1.f : -1.f;
            kadd(As, Ac, sgn * ps[P_SW + kk] * w1v);
            kadd(Bs, Bc, sgn * ps[P_SC + kk] * w1v);
            tab[(size_t)s * (2 * HDIM) + j] = As + Ac;
            tab[(size_t)s * (2 * HDIM) + HDIM + j] = Bs + Bc + bj;
        }
    }
}

// ============ E1: PWL h1 + emb -> g_e (R12 version, unchanged) ============
#define E1_W2   0
#define E1_T    4096
#define E1_OB   12288
#define E1_SMEM_FLOATS 12416
#define E1_SMEM_BYTES  (E1_SMEM_FLOATS * 4)

__global__ __launch_bounds__(512, 2)
void enc_emb_kernel(const float* __restrict__ obs,
                    const float* __restrict__ W2,
                    const float* __restrict__ b2)
{
    extern __shared__ float sm[];
    const int tid  = threadIdx.x;
    const int base = blockIdx.x * 128;

    if (tid < 128) sm[E1_OB + tid] = obs[base + tid];
    for (int idx = tid; idx < HDIM * CDIM; idx += 512) {
        int c = idx >> 4, jf = idx & 15;
        int lp = jf >> 2;
        int pp = (lp + (c >> 6)) & 3;
        sm[E1_W2 + c * 16 + pp * 4 + (jf & 3)] = W2[idx];
    }
    for (int i = tid; i < OBSD * HDIM; i += 512) sm[E1_T + i] = g_t[i];
    __syncthreads();

    const int r = tid >> 2, q = tid & 3;
    const int d = (base + r) & (OBSD - 1);
    const float x = sm[E1_OB + r];
    const float* td = sm + E1_T + d * HDIM;
    int seg;
    if (td[HDIM - 1] < x) seg = HDIM;
    else {
        seg = 0;
        #pragma unroll
        for (int w = HDIM / 2; w >= 1; w >>= 1)
            if (td[seg + w - 1] < x) seg += w;
    }
    const float* tab = g_tab + (size_t)(d * (HDIM + 1) + seg) * (2 * HDIM);

    u64 e2[8];
    if (q == 0) {
        const u64* bp = (const u64*)b2;
        #pragma unroll
        for (int k = 0; k < 8; k++) e2[k] = bp[k];
    } else {
        #pragma unroll
        for (int k = 0; k < 8; k++) e2[k] = 0ull;
    }
    const float4* Ap = (const float4*)(tab + q * 64);
    const float4* Bp = (const float4*)(tab + HDIM + q * 64);
    #pragma unroll 4
    for (int i4 = 0; i4 < 16; i4++) {
        float4 a = Ap[i4];
        float4 b = Bp[i4];
        float hv[4];
        hv[0] = fmaxf(fmaf(a.x, x, b.x), 0.f);
        hv[1] = fmaxf(fmaf(a.y, x, b.y), 0.f);
        hv[2] = fmaxf(fmaf(a.z, x, b.z), 0.f);
        hv[3] = fmaxf(fmaf(a.w, x, b.w), 0.f);
        #pragma unroll
        for (int m = 0; m < 4; m++) {
            int c = q * 64 + i4 * 4 + m;
            u64 h2 = f2pack(hv[m], hv[m]);
            const float* wrow = sm + E1_W2 + c * 16;
            #pragma unroll
            for (int lp = 0; lp < 4; lp++) {
                ulonglong2 w = *(const ulonglong2*)(wrow + ((lp + q) & 3) * 4);
                e2[2 * lp]     = ffma2(h2, w.x, e2[2 * lp]);
                e2[2 * lp + 1] = ffma2(h2, w.y, e2[2 * lp + 1]);
            }
        }
    }
    #pragma unroll
    for (int off = 1; off < 4; off <<= 1)
        #pragma unroll
        for (int k = 0; k < 8; k++)
            e2[k] = fadd2(e2[k], shfl_xor_u64(e2[k], off));
    if (q == 0) {
        ulonglong2* ep = (ulonglong2*)&g_e[(size_t)(base + r) * CDIM];
        ep[0] = make_ulonglong2(e2[0], e2[1]);
        ep[1] = make_ulonglong2(e2[2], e2[3]);
        ep[2] = make_ulonglong2(e2[4], e2[5]);
        ep[3] = make_ulonglong2(e2[6], e2[7]);
    }
}

// ============ E2 v3: distance as dec-style GEMM (transposed operands, FFMA2) ============
// block: 16 rows x 512 codes, 256 threads. warp w: rows (w>>1)*4..+3, code half (w&1).
// lane l: code pairs cbase+64i, cbase = ch*256 + 2l.
__global__ __launch_bounds__(256)
void enc_dist_kernel(const float* __restrict__ cb)
{
    __shared__ float cbt[16 * 512];    // cbt[k][j] = cb[j][k]
    __shared__ float set[16 * 20];     // set[k][r] = e[base+r][k]
    __shared__ float cn[NCODE];
    __shared__ u64   part[16][2];
    __shared__ int   jb[16];
    const int tid  = threadIdx.x;
    const int base = blockIdx.x * 16;

    // stage codebook transposed (coalesced LDG.128, conflict-free STS)
    for (int t = tid; t < NCODE * CDIM / 4; t += 256) {
        int j = t >> 2, q4 = t & 3;
        float4 v = ((const float4*)cb)[t];
        cbt[(q4 * 4 + 0) * 512 + j] = v.x;
        cbt[(q4 * 4 + 1) * 512 + j] = v.y;
        cbt[(q4 * 4 + 2) * 512 + j] = v.z;
        cbt[(q4 * 4 + 3) * 512 + j] = v.w;
    }
    // stage e^T
    if (tid < 64) {
        int r = tid >> 2, q4 = tid & 3;
        float4 v = *(const float4*)&g_e[(size_t)(base + r) * CDIM + q4 * 4];
        set[(q4 * 4 + 0) * 20 + r] = v.x;
        set[(q4 * 4 + 1) * 20 + r] = v.y;
        set[(q4 * 4 + 2) * 20 + r] = v.z;
        set[(q4 * 4 + 3) * 20 + r] = v.w;
    }
    __syncthreads();
    // code norms
    for (int j = tid; j < NCODE; j += 256) {
        float s = 0.f;
        #pragma unroll
        for (int k = 0; k < CDIM; k++) { float v = cbt[k * 512 + j]; s = fmaf(v, v, s); }
        cn[j] = s;
    }
    __syncthreads();

    const int w = tid >> 5, l = tid & 31;
    const int rg = w >> 1;                 // 0..3 -> rows rg*4..+3
    const int ch = w & 1;                  // code half
    const int cbase = ch * 256 + l * 2;

    u64 acc[4][4];                         // [row][code-pair group]
    #pragma unroll
    for (int r = 0; r < 4; r++)
        #pragma unroll
        for (int i = 0; i < 4; i++) acc[r][i] = 0ull;

    #pragma unroll
    for (int k = 0; k < CDIM; k++) {
        float4 av = *(const float4*)&set[k * 20 + rg * 4];        // broadcast
        const float* crow = &cbt[k * 512 + cbase];
        u64 c0 = *(const u64*)(crow);
        u64 c1 = *(const u64*)(crow + 64);
        u64 c2 = *(const u64*)(crow + 128);
        u64 c3 = *(const u64*)(crow + 192);
        u64 a0 = f2pack(av.x, av.x);
        u64 a1 = f2pack(av.y, av.y);
        u64 a2 = f2pack(av.z, av.z);
        u64 a3 = f2pack(av.w, av.w);
        acc[0][0] = ffma2(a0, c0, acc[0][0]); acc[0][1] = ffma2(a0, c1, acc[0][1]);
        acc[0][2] = ffma2(a0, c2, acc[0][2]); acc[0][3] = ffma2(a0, c3, acc[0][3]);
        acc[1][0] = ffma2(a1, c0, acc[1][0]); acc[1][1] = ffma2(a1, c1, acc[1][1]);
        acc[1][2] = ffma2(a1, c2, acc[1][2]); acc[1][3] = ffma2(a1, c3, acc[1][3]);
        acc[2][0] = ffma2(a2, c0, acc[2][0]); acc[2][1] = ffma2(a2, c1, acc[2][1]);
        acc[2][2] = ffma2(a2, c2, acc[2][2]); acc[2][3] = ffma2(a2, c3, acc[2][3]);
        acc[3][0] = ffma2(a3, c0, acc[3][0]); acc[3][1] = ffma2(a3, c1, acc[3][1]);
        acc[3][2] = ffma2(a3, c2, acc[3][2]); acc[3][3] = ffma2(a3, c3, acc[3][3]);
    }

    // finalize: dist = cn[j] - 2*dot ; ascending-j strict < keeps lowest idx
    float best[4]; int bi[4];
    #pragma unroll
    for (int r = 0; r < 4; r++) { best[r] = CUDART_INF_F; bi[r] = NCODE; }
    #pragma unroll
    for (int i = 0; i < 4; i++) {
        int jlo = cbase + i * 64;
        float nlo = cn[jlo], nhi = cn[jlo + 1];
        #pragma unroll
        for (int r = 0; r < 4; r++) {
            u64 a = acc[r][i];
            float dlo = fmaf(-2.f, f2lo(a), nlo);
            float dhi = fmaf(-2.f, f2hi(a), nhi);
            if (dlo < best[r]) { best[r] = dlo; bi[r] = jlo; }
            if (dhi < best[r]) { best[r] = dhi; bi[r] = jlo + 1; }
        }
    }
    // warp butterfly, lexicographic (val, idx)
    #pragma unroll
    for (int off = 1; off < 32; off <<= 1) {
        #pragma unroll
        for (int r = 0; r < 4; r++) {
            float ob = __shfl_xor_sync(0xffffffffu, best[r], off);
            int   oi = __shfl_xor_sync(0xffffffffu, bi[r],   off);
            if (ob < best[r] || (ob == best[r] && oi < bi[r])) { best[r] = ob; bi[r] = oi; }
        }
    }
    if (l == 0) {
        #pragma unroll
        for (int r = 0; r < 4; r++) {
            unsigned u = __float_as_uint(best[r]);
            unsigned key = u ^ (unsigned)(((int)u >> 31) | 0x80000000);
            part[rg * 4 + r][ch] = ((u64)key << 32) | (unsigned)bi[r];
        }
    }
    __syncthreads();
    if (tid < 16) {
        u64 a = part[tid][0], b = part[tid][1];
        jb[tid] = (int)(unsigned)((a < b) ? a : b);
    }
    __syncthreads();
    if (tid < 64) {
        int r = tid >> 2, q4 = tid & 3;
        int j = jb[r];
        float4 v = *(const float4*)&cb[(size_t)j * CDIM + q4 * 4];
        *(float4*)&g_q[(size_t)(base + r) * CDIM + q4 * 4] = v;
    }
}

// ---------------- decoder (R12/R9 version, unchanged) ----------------
#define D_ST    0
#define D_SA    9216
#define D_SB    10368
#define D_SMEM_FLOATS 18560
#define D_SMEM_BYTES  (D_SMEM_FLOATS * 4)

__global__ __launch_bounds__(DTHREADS, 2)
void dec_kernel(const float* __restrict__ W0,
                const float* __restrict__ b0,
                const float* __restrict__ W1,
                const float* __restrict__ b1,
                const float* __restrict__ W2,
                const float* __restrict__ b2,
                float* __restrict__ out)
{
    extern __shared__ float sm[];
    const int tid  = threadIdx.x;
    const int base = blockIdx.x * DTR;
    const int cg   = tid & 31;
    const int rg   = tid >> 5;

    float acc[4][8];
    #pragma unroll
    for (int i = 0; i < 4; i++)
        #pragma unroll
        for (int j = 0; j < 8; j++) acc[i][j] = 0.f;

    for (int k0 = 0; k0 < 2 * HDIM; k0 += KC) {
        __syncthreads();
        {
            int r   = tid >> 3;
            int kk0 = (tid & 7) << 2;
            const float* src = g_q + (size_t)(base + r) * (2 * HDIM) + k0 + kk0;
            float4 v = *(const float4*)src;
            sm[D_SA + (kk0 + 0) * 36 + r] = v.x;
            sm[D_SA + (kk0 + 1) * 36 + r] = v.y;
            sm[D_SA + (kk0 + 2) * 36 + r] = v.z;
            sm[D_SA + (kk0 + 3) * 36 + r] = v.w;
        }
        {
            const float4* s = (const float4*)(W0 + k0 * HDIM);
            float4* d = (float4*)(sm + D_SB);
            #pragma unroll
            for (int i = 0; i < 8; i++) d[tid + i * DTHREADS] = s[tid + i * DTHREADS];
        }
        __syncthreads();
        #pragma unroll 8
        for (int kk = 0; kk < KC; kk++) {
            float4 av = *(const float4*)&sm[D_SA + kk * 36 + rg * 4];
            float a[4] = {av.x, av.y, av.z, av.w};
            float bb[8];
            #pragma unroll
            for (int i = 0; i < 8; i++) bb[i] = sm[D_SB + kk * HDIM + cg + 32 * i];
            #pragma unroll
            for (int ri = 0; ri < 4; ri++)
                #pragma unroll
                for (int ci = 0; ci < 8; ci++)
                    acc[ri][ci] = fmaf(a[ri], bb[ci], acc[ri][ci]);
        }
    }
    __syncthreads();
    {
        float bb[8];
        #pragma unroll
        for (int ci = 0; ci < 8; ci++) bb[ci] = b0[cg + 32 * ci];
        #pragma unroll
        for (int ci = 0; ci < 8; ci++) {
            int c = cg + 32 * ci;
            #pragma unroll
            for (int ri = 0; ri < 4; ri++)
                sm[D_ST + c * 36 + rg * 4 + ri] = fmaxf(acc[ri][ci] + bb[ci], 0.f);
        }
        #pragma unroll
        for (int i = 0; i < 4; i++)
            #pragma unroll
            for (int j = 0; j < 8; j++) acc[i][j] = 0.f;
    }

    for (int k0 = 0; k0 < HDIM; k0 += KC) {
        __syncthreads();
        {
            const float4* s = (const float4*)(W1 + k0 * HDIM);
            float4* d = (float4*)(sm + D_SB);
            #pragma unroll
            for (int i = 0; i < 8; i++) d[tid + i * DTHREADS] = s[tid + i * DTHREADS];
        }
        __syncthreads();
        #pragma unroll 8
        for (int kk = 0; kk < KC; kk++) {
            int k = k0 + kk;
            float4 av = *(const float4*)&sm[D_ST + k * 36 + rg * 4];
            float a[4] = {av.x, av.y, av.z, av.w};
            float bb[8];
            #pragma unroll
            for (int i = 0; i < 8; i++) bb[i] = sm[D_SB + kk * HDIM + cg + 32 * i];
            #pragma unroll
            for (int ri = 0; ri < 4; ri++)
                #pragma unroll
                for (int ci = 0; ci < 8; ci++)
                    acc[ri][ci] = fmaf(a[ri], bb[ci], acc[ri][ci]);
        }
    }
    __syncthreads();
    {
        float bb[8];
        #pragma unroll
        for (int ci = 0; ci < 8; ci++) bb[ci] = b1[cg + 32 * ci];
        #pragma unroll
        for (int ri = 0; ri < 4; ri++)
            #pragma unroll
            for (int ci = 0; ci < 8; ci++)
                sm[D_ST + (rg * 4 + ri) * 260 + cg + 32 * ci] =
                    fmaxf(acc[ri][ci] + bb[ci], 0.f);
        const float4* s = (const float4*)W2;
        float4* d = (float4*)(sm + D_SB);
        #pragma unroll
        for (int i = 0; i < 8; i++) d[tid + i * DTHREADS] = s[tid + i * DTHREADS];
    }
    __syncthreads();
    {
        int r = tid >> 3, part = tid & 7;
        int o0 = part * 4;
        float o[4];
        #pragma unroll
        for (int i = 0; i < 4; i++) o[i] = b2[o0 + i];
        #pragma unroll 4
        for (int c = 0; c < HDIM; c++) {
            float h = sm[D_ST + r * 260 + c];
            #pragma unroll
            for (int i = 0; i < 4; i++)
                o[i] = fmaf(h, sm[D_SB + c * OBSD + o0 + i], o[i]);
        }
        float4* dst = (float4*)&out[(size_t)(base + r) * OBSD + o0];
        *dst = make_float4(o[0], o[1], o[2], o[3]);
    }
}

// ======================= launcher =======================
extern "C" void kernel_launch(void* const* d_in, const int* in_sizes, int n_in,
                              void* d_out, int out_size) {
    (void)in_sizes; (void)n_in; (void)out_size;
    const float* obs = (const float*)d_in[0];
    const float* eW0 = (const float*)d_in[1];
    const float* eb0 = (const float*)d_in[2];
    const float* eW1 = (const float*)d_in[3];
    const float* eb1 = (const float*)d_in[4];
    const float* eW2 = (const float*)d_in[5];
    const float* eb2 = (const float*)d_in[6];
    const float* dW0 = (const float*)d_in[7];
    const float* db0 = (const float*)d_in[8];
    const float* dW1 = (const float*)d_in[9];
    const float* db1 = (const float*)d_in[10];
    const float* dW2 = (const float*)d_in[11];
    const float* db2 = (const float*)d_in[12];
    const float* cb  = (const float*)d_in[13];
    float* out = (float*)d_out;

    cudaFuncSetAttribute(pwl_build_kernel,
                         cudaFuncAttributeMaxDynamicSharedMemorySize, P_SMEM_BYTES);
    cudaFuncSetAttribute(enc_emb_kernel,
                         cudaFuncAttributeMaxDynamicSharedMemorySize, E1_SMEM_BYTES);
    cudaFuncSetAttribute(dec_kernel,
                         cudaFuncAttributeMaxDynamicSharedMemorySize, D_SMEM_BYTES);

    pwl_build_kernel<<<OBSD * 4, 256, P_SMEM_BYTES>>>(eW0, eb0, eW1, eb1);
    enc_emb_kernel<<<ROWS / 128, 512, E1_SMEM_BYTES>>>(obs, eW2, eb2);
    enc_dist_kernel<<<ROWS / 16, 256>>>(cb);
    dec_kernel<<<BATCH / DTR, DTHREADS, D_SMEM_BYTES>>>(
        dW0, db0, dW1, db1, dW2, db2, out);
}

// round 17
// speedup vs baseline: 1.7696x; 1.1237x over previous
#include <cuda_runtime.h>
#include <math_constants.h>

#define BATCH    8192
#define OBSD     32
#define HDIM     256
#define CDIM     16
#define NCODE    512
#define ROWS     (BATCH * OBSD)

#define DTR      32
#define DTHREADS 256
#define KC       32

__device__ float g_q[(size_t)ROWS * CDIM];
__device__ float g_e[(size_t)ROWS * CDIM];
__device__ float g_t[OBSD * HDIM];
__device__ float g_tab[(size_t)OBSD * (HDIM + 1) * (2 * HDIM)];

typedef unsigned long long u64;
__device__ __forceinline__ u64 f2pack(float lo, float hi) {
    u64 r; asm("mov.b64 %0, {%1, %2};" : "=l"(r) : "f"(lo), "f"(hi)); return r;
}
__device__ __forceinline__ u64 ffma2(u64 a, u64 b, u64 c) {
    u64 d; asm("fma.rn.f32x2 %0, %1, %2, %3;" : "=l"(d) : "l"(a), "l"(b), "l"(c)); return d;
}
__device__ __forceinline__ u64 fmul2(u64 a, u64 b) {
    u64 d; asm("mul.rn.f32x2 %0, %1, %2;" : "=l"(d) : "l"(a), "l"(b)); return d;
}
__device__ __forceinline__ u64 fadd2(u64 a, u64 b) {
    u64 d; asm("add.rn.f32x2 %0, %1, %2;" : "=l"(d) : "l"(a), "l"(b)); return d;
}
__device__ __forceinline__ float f2lo(u64 v) { return __uint_as_float((unsigned)v); }
__device__ __forceinline__ float f2hi(u64 v) { return __uint_as_float((unsigned)(v >> 32)); }
__device__ __forceinline__ u64 shfl_xor_u64(u64 v, int off) {
    unsigned lo = __shfl_xor_sync(0xffffffffu, (unsigned)v, off);
    unsigned hi = __shfl_xor_sync(0xffffffffu, (unsigned)(v >> 32), off);
    return ((u64)hi << 32) | lo;
}
__device__ __forceinline__ void kadd(float& s, float& c, float y) {
    float t = s + y;
    c += (fabsf(s) >= fabsf(y)) ? ((s - t) + y) : ((y - t) + s);
    s = t;
}

// ============ PWL builder (unchanged) ============
#define P_ST   0
#define P_SW   256
#define P_SC   512
#define P_ORD  768
#define P_ACT  1024
#define P_W1S  1280
#define P_SMEM_FLOATS (1280 + 256 * 64)
#define P_SMEM_BYTES  (P_SMEM_FLOATS * 4)

__global__ __launch_bounds__(256, 1)
void pwl_build_kernel(const float* __restrict__ W0,
                      const float* __restrict__ b0,
                      const float* __restrict__ W1,
                      const float* __restrict__ b1)
{
    extern __shared__ float ps[];
    int*  pord = (int*)(ps + P_ORD);
    int*  pact = (int*)(ps + P_ACT);
    const int d  = blockIdx.x >> 2;
    const int jq = blockIdx.x & 3;
    const int t  = threadIdx.x;

    {
        float w = W0[t];
        float c = W0[(1 + d) * HDIM + t] + b0[t];
        int act; float tv;
        if (w > 0.f)      { act = 1; tv = -c / w; }
        else if (w < 0.f) { act = 0; tv = -c / w; }
        else              { act = (c <= 0.f) ? 1 : 0; tv = CUDART_INF_F; }
        ps[P_ST + t] = tv; ps[P_SW + t] = w; ps[P_SC + t] = c; pact[t] = act;
    }
    {
        const float4* src = (const float4*)(W1 + t * HDIM + jq * 64);
        float4* dst = (float4*)(ps + P_W1S + t * 64);
        #pragma unroll
        for (int i = 0; i < 16; i++) dst[i] = src[i];
    }
    __syncthreads();
    {
        float tv = ps[P_ST + t];
        int rank = 0;
        for (int k2 = 0; k2 < HDIM; k2++) {
            float t2 = ps[P_ST + k2];
            rank += (t2 < tv || (t2 == tv && k2 < t)) ? 1 : 0;
        }
        pord[rank] = t;
        if (jq == 0) g_t[d * HDIM + rank] = tv;
    }
    __syncthreads();

    if (t < 64) {
        const int j = jq * 64 + t;
        float As = 0.f, Ac = 0.f, Bs = 0.f, Bc = 0.f;
        for (int kk = 0; kk < HDIM; kk++) {
            if (!pact[kk]) {
                float w1v = ps[P_W1S + kk * 64 + t];
                kadd(As, Ac, ps[P_SW + kk] * w1v);
                kadd(Bs, Bc, ps[P_SC + kk] * w1v);
            }
        }
        const float bj = b1[j];
        float* tab = g_tab + (size_t)d * (HDIM + 1) * (2 * HDIM);
        tab[j] = As + Ac;
        tab[HDIM + j] = Bs + Bc + bj;
        for (int s = 1; s <= HDIM; s++) {
            int kk = pord[s - 1];
            float w1v = ps[P_W1S + kk * 64 + t];
            float sgn = pact[kk] ? 1.f : -1.f;
            kadd(As, Ac, sgn * ps[P_SW + kk] * w1v);
            kadd(Bs, Bc, sgn * ps[P_SC + kk] * w1v);
            tab[(size_t)s * (2 * HDIM) + j] = As + Ac;
            tab[(size_t)s * (2 * HDIM) + HDIM + j] = Bs + Bc + bj;
        }
    }
}

// ============ E1: PWL h1 + emb -> g_e (unchanged) ============
#define E1_W2   0
#define E1_T    4096
#define E1_OB   12288
#define E1_SMEM_FLOATS 12416
#define E1_SMEM_BYTES  (E1_SMEM_FLOATS * 4)

__global__ __launch_bounds__(512, 2)
void enc_emb_kernel(const float* __restrict__ obs,
                    const float* __restrict__ W2,
                    const float* __restrict__ b2)
{
    extern __shared__ float sm[];
    const int tid  = threadIdx.x;
    const int base = blockIdx.x * 128;

    if (tid < 128) sm[E1_OB + tid] = obs[base + tid];
    for (int idx = tid; idx < HDIM * CDIM; idx += 512) {
        int c = idx >> 4, jf = idx & 15;
        int lp = jf >> 2;
        int pp = (lp + (c >> 6)) & 3;
        sm[E1_W2 + c * 16 + pp * 4 + (jf & 3)] = W2[idx];
    }
    for (int i = tid; i < OBSD * HDIM; i += 512) sm[E1_T + i] = g_t[i];
    __syncthreads();

    const int r = tid >> 2, q = tid & 3;
    const int d = (base + r) & (OBSD - 1);
    const float x = sm[E1_OB + r];
    const float* td = sm + E1_T + d * HDIM;
    int seg;
    if (td[HDIM - 1] < x) seg = HDIM;
    else {
        seg = 0;
        #pragma unroll
        for (int w = HDIM / 2; w >= 1; w >>= 1)
            if (td[seg + w - 1] < x) seg += w;
    }
    const float* tab = g_tab + (size_t)(d * (HDIM + 1) + seg) * (2 * HDIM);

    u64 e2[8];
    if (q == 0) {
        const u64* bp = (const u64*)b2;
        #pragma unroll
        for (int k = 0; k < 8; k++) e2[k] = bp[k];
    } else {
        #pragma unroll
        for (int k = 0; k < 8; k++) e2[k] = 0ull;
    }
    const float4* Ap = (const float4*)(tab + q * 64);
    const float4* Bp = (const float4*)(tab + HDIM + q * 64);
    #pragma unroll 4
    for (int i4 = 0; i4 < 16; i4++) {
        float4 a = Ap[i4];
        float4 b = Bp[i4];
        float hv[4];
        hv[0] = fmaxf(fmaf(a.x, x, b.x), 0.f);
        hv[1] = fmaxf(fmaf(a.y, x, b.y), 0.f);
        hv[2] = fmaxf(fmaf(a.z, x, b.z), 0.f);
        hv[3] = fmaxf(fmaf(a.w, x, b.w), 0.f);
        #pragma unroll
        for (int m = 0; m < 4; m++) {
            int c = q * 64 + i4 * 4 + m;
            u64 h2 = f2pack(hv[m], hv[m]);
            const float* wrow = sm + E1_W2 + c * 16;
            #pragma unroll
            for (int lp = 0; lp < 4; lp++) {
                ulonglong2 w = *(const ulonglong2*)(wrow + ((lp + q) & 3) * 4);
                e2[2 * lp]     = ffma2(h2, w.x, e2[2 * lp]);
                e2[2 * lp + 1] = ffma2(h2, w.y, e2[2 * lp + 1]);
            }
        }
    }
    #pragma unroll
    for (int off = 1; off < 4; off <<= 1)
        #pragma unroll
        for (int k = 0; k < 8; k++)
            e2[k] = fadd2(e2[k], shfl_xor_u64(e2[k], off));
    if (q == 0) {
        ulonglong2* ep = (ulonglong2*)&g_e[(size_t)(base + r) * CDIM];
        ep[0] = make_ulonglong2(e2[0], e2[1]);
        ep[1] = make_ulonglong2(e2[2], e2[3]);
        ep[2] = make_ulonglong2(e2[4], e2[5]);
        ep[3] = make_ulonglong2(e2[6], e2[7]);
    }
}

// ============ E2 v4: GEMM distance, 128 rows/block, codebook staged ONCE ============
// 8 tiles of 16 rows over resident cbt. Hot loop identical to v3.
#define E2_ROWS  128
#define E2_TILES 8

__global__ __launch_bounds__(256)
void enc_dist_kernel(const float* __restrict__ cb)
{
    __shared__ float cbt[16 * 512];     // 32768 B : cbt[k][j] = cb[j][k]
    __shared__ float set[16 * 132];     //  8448 B : set[k][r] = e[base+r][k]
    __shared__ float cn[NCODE];         //  2048 B
    __shared__ u64   part[16][2];
    __shared__ int   jb[E2_ROWS];
    const int tid  = threadIdx.x;
    const int base = blockIdx.x * E2_ROWS;

    // stage codebook transposed (once per 128 rows)
    for (int t = tid; t < NCODE * CDIM / 4; t += 256) {
        int j = t >> 2, q4 = t & 3;
        float4 v = ((const float4*)cb)[t];
        cbt[(q4 * 4 + 0) * 512 + j] = v.x;
        cbt[(q4 * 4 + 1) * 512 + j] = v.y;
        cbt[(q4 * 4 + 2) * 512 + j] = v.z;
        cbt[(q4 * 4 + 3) * 512 + j] = v.w;
    }
    // stage e^T for 128 rows
    for (int t = tid; t < E2_ROWS * 4; t += 256) {
        int r = t >> 2, q4 = t & 3;
        float4 v = *(const float4*)&g_e[(size_t)(base + r) * CDIM + q4 * 4];
        set[(q4 * 4 + 0) * 132 + r] = v.x;
        set[(q4 * 4 + 1) * 132 + r] = v.y;
        set[(q4 * 4 + 2) * 132 + r] = v.z;
        set[(q4 * 4 + 3) * 132 + r] = v.w;
    }
    __syncthreads();
    // code norms
    for (int j = tid; j < NCODE; j += 256) {
        float s = 0.f;
        #pragma unroll
        for (int k = 0; k < CDIM; k++) { float v = cbt[k * 512 + j]; s = fmaf(v, v, s); }
        cn[j] = s;
    }
    __syncthreads();

    const int w = tid >> 5, l = tid & 31;
    const int rg = w >> 1;                 // 0..3
    const int ch = w & 1;                  // code half
    const int cbase = ch * 256 + l * 2;

    for (int rt = 0; rt < E2_TILES; rt++) {
        const int r0 = rt * 16 + rg * 4;   // this warp's 4 rows within block

        u64 acc[4][4];
        #pragma unroll
        for (int r = 0; r < 4; r++)
            #pragma unroll
            for (int i = 0; i < 4; i++) acc[r][i] = 0ull;

        #pragma unroll
        for (int k = 0; k < CDIM; k++) {
            float4 av = *(const float4*)&set[k * 132 + r0];       // broadcast
            const float* crow = &cbt[k * 512 + cbase];
            u64 c0 = *(const u64*)(crow);
            u64 c1 = *(const u64*)(crow + 64);
            u64 c2 = *(const u64*)(crow + 128);
            u64 c3 = *(const u64*)(crow + 192);
            u64 a0 = f2pack(av.x, av.x);
            u64 a1 = f2pack(av.y, av.y);
            u64 a2 = f2pack(av.z, av.z);
            u64 a3 = f2pack(av.w, av.w);
            acc[0][0] = ffma2(a0, c0, acc[0][0]); acc[0][1] = ffma2(a0, c1, acc[0][1]);
            acc[0][2] = ffma2(a0, c2, acc[0][2]); acc[0][3] = ffma2(a0, c3, acc[0][3]);
            acc[1][0] = ffma2(a1, c0, acc[1][0]); acc[1][1] = ffma2(a1, c1, acc[1][1]);
            acc[1][2] = ffma2(a1, c2, acc[1][2]); acc[1][3] = ffma2(a1, c3, acc[1][3]);
            acc[2][0] = ffma2(a2, c0, acc[2][0]); acc[2][1] = ffma2(a2, c1, acc[2][1]);
            acc[2][2] = ffma2(a2, c2, acc[2][2]); acc[2][3] = ffma2(a2, c3, acc[2][3]);
            acc[3][0] = ffma2(a3, c0, acc[3][0]); acc[3][1] = ffma2(a3, c1, acc[3][1]);
            acc[3][2] = ffma2(a3, c2, acc[3][2]); acc[3][3] = ffma2(a3, c3, acc[3][3]);
        }

        float best[4]; int bi[4];
        #pragma unroll
        for (int r = 0; r < 4; r++) { best[r] = CUDART_INF_F; bi[r] = NCODE; }
        #pragma unroll
        for (int i = 0; i < 4; i++) {
            int jlo = cbase + i * 64;
            float nlo = cn[jlo], nhi = cn[jlo + 1];
            #pragma unroll
            for (int r = 0; r < 4; r++) {
                u64 a = acc[r][i];
                float dlo = fmaf(-2.f, f2lo(a), nlo);
                float dhi = fmaf(-2.f, f2hi(a), nhi);
                if (dlo < best[r]) { best[r] = dlo; bi[r] = jlo; }
                if (dhi < best[r]) { best[r] = dhi; bi[r] = jlo + 1; }
            }
        }
        #pragma unroll
        for (int off = 1; off < 32; off <<= 1) {
            #pragma unroll
            for (int r = 0; r < 4; r++) {
                float ob = __shfl_xor_sync(0xffffffffu, best[r], off);
                int   oi = __shfl_xor_sync(0xffffffffu, bi[r],   off);
                if (ob < best[r] || (ob == best[r] && oi < bi[r])) { best[r] = ob; bi[r] = oi; }
            }
        }
        if (l == 0) {
            #pragma unroll
            for (int r = 0; r < 4; r++) {
                unsigned u = __float_as_uint(best[r]);
                unsigned key = u ^ (unsigned)(((int)u >> 31) | 0x80000000);
                part[rg * 4 + r][ch] = ((u64)key << 32) | (unsigned)bi[r];
            }
        }
        __syncthreads();
        if (tid < 16) {
            u64 a = part[tid][0], b = part[tid][1];
            jb[rt * 16 + tid] = (int)(unsigned)((a < b) ? a : b);
        }
        __syncthreads();
    }

    // write q for all 128 rows
    for (int t = tid; t < E2_ROWS * 4; t += 256) {
        int r = t >> 2, q4 = t & 3;
        int j = jb[r];
        float4 v = *(const float4*)&cb[(size_t)j * CDIM + q4 * 4];
        *(float4*)&g_q[(size_t)(base + r) * CDIM + q4 * 4] = v;
    }
}

// ---------------- decoder (unchanged) ----------------
#define D_ST    0
#define D_SA    9216
#define D_SB    10368
#define D_SMEM_FLOATS 18560
#define D_SMEM_BYTES  (D_SMEM_FLOATS * 4)

__global__ __launch_bounds__(DTHREADS, 2)
void dec_kernel(const float* __restrict__ W0,
                const float* __restrict__ b0,
                const float* __restrict__ W1,
                const float* __restrict__ b1,
                const float* __restrict__ W2,
                const float* __restrict__ b2,
                float* __restrict__ out)
{
    extern __shared__ float sm[];
    const int tid  = threadIdx.x;
    const int base = blockIdx.x * DTR;
    const int cg   = tid & 31;
    const int rg   = tid >> 5;

    float acc[4][8];
    #pragma unroll
    for (int i = 0; i < 4; i++)
        #pragma unroll
        for (int j = 0; j < 8; j++) acc[i][j] = 0.f;

    for (int k0 = 0; k0 < 2 * HDIM; k0 += KC) {
        __syncthreads();
        {
            int r   = tid >> 3;
            int kk0 = (tid & 7) << 2;
            const float* src = g_q + (size_t)(base + r) * (2 * HDIM) + k0 + kk0;
            float4 v = *(const float4*)src;
            sm[D_SA + (kk0 + 0) * 36 + r] = v.x;
            sm[D_SA + (kk0 + 1) * 36 + r] = v.y;
            sm[D_SA + (kk0 + 2) * 36 + r] = v.z;
            sm[D_SA + (kk0 + 3) * 36 + r] = v.w;
        }
        {
            const float4* s = (const float4*)(W0 + k0 * HDIM);
            float4* d = (float4*)(sm + D_SB);
            #pragma unroll
            for (int i = 0; i < 8; i++) d[tid + i * DTHREADS] = s[tid + i * DTHREADS];
        }
        __syncthreads();
        #pragma unroll 8
        for (int kk = 0; kk < KC; kk++) {
            float4 av = *(const float4*)&sm[D_SA + kk * 36 + rg * 4];
            float a[4] = {av.x, av.y, av.z, av.w};
            float bb[8];
            #pragma unroll
            for (int i = 0; i < 8; i++) bb[i] = sm[D_SB + kk * HDIM + cg + 32 * i];
            #pragma unroll
            for (int ri = 0; ri < 4; ri++)
                #pragma unroll
                for (int ci = 0; ci < 8; ci++)
                    acc[ri][ci] = fmaf(a[ri], bb[ci], acc[ri][ci]);
        }
    }
    __syncthreads();
    {
        float bb[8];
        #pragma unroll
        for (int ci = 0; ci < 8; ci++) bb[ci] = b0[cg + 32 * ci];
        #pragma unroll
        for (int ci = 0; ci < 8; ci++) {
            int c = cg + 32 * ci;
            #pragma unroll
            for (int ri = 0; ri < 4; ri++)
                sm[D_ST + c * 36 + rg * 4 + ri] = fmaxf(acc[ri][ci] + bb[ci], 0.f);
        }
        #pragma unroll
        for (int i = 0; i < 4; i++)
            #pragma unroll
            for (int j = 0; j < 8; j++) acc[i][j] = 0.f;
    }

    for (int k0 = 0; k0 < HDIM; k0 += KC) {
        __syncthreads();
        {
            const float4* s = (const float4*)(W1 + k0 * HDIM);
            float4* d = (float4*)(sm + D_SB);
            #pragma unroll
            for (int i = 0; i < 8; i++) d[tid + i * DTHREADS] = s[tid + i * DTHREADS];
        }
        __syncthreads();
        #pragma unroll 8
        for (int kk = 0; kk < KC; kk++) {
            int k = k0 + kk;
            float4 av = *(const float4*)&sm[D_ST + k * 36 + rg * 4];
            float a[4] = {av.x, av.y, av.z, av.w};
            float bb[8];
            #pragma unroll
            for (int i = 0; i < 8; i++) bb[i] = sm[D_SB + kk * HDIM + cg + 32 * i];
            #pragma unroll
            for (int ri = 0; ri < 4; ri++)
                #pragma unroll
                for (int ci = 0; ci < 8; ci++)
                    acc[ri][ci] = fmaf(a[ri], bb[ci], acc[ri][ci]);
        }
    }
    __syncthreads();
    {
        float bb[8];
        #pragma unroll
        for (int ci = 0; ci < 8; ci++) bb[ci] = b1[cg + 32 * ci];
        #pragma unroll
        for (int ri = 0; ri < 4; ri++)
            #pragma unroll
            for (int ci = 0; ci < 8; ci++)
                sm[D_ST + (rg * 4 + ri) * 260 + cg + 32 * ci] =
                    fmaxf(acc[ri][ci] + bb[ci], 0.f);
        const float4* s = (const float4*)W2;
        float4* d = (float4*)(sm + D_SB);
        #pragma unroll
        for (int i = 0; i < 8; i++) d[tid + i * DTHREADS] = s[tid + i * DTHREADS];
    }
    __syncthreads();
    {
        int r = tid >> 3, part = tid & 7;
        int o0 = part * 4;
        float o[4];
        #pragma unroll
        for (int i = 0; i < 4; i++) o[i] = b2[o0 + i];
        #pragma unroll 4
        for (int c = 0; c < HDIM; c++) {
            float h = sm[D_ST + r * 260 + c];
            #pragma unroll
            for (int i = 0; i < 4; i++)
                o[i] = fmaf(h, sm[D_SB + c * OBSD + o0 + i], o[i]);
        }
        float4* dst = (float4*)&out[(size_t)(base + r) * OBSD + o0];
        *dst = make_float4(o[0], o[1], o[2], o[3]);
    }
}

// ======================= launcher =======================
extern "C" void kernel_launch(void* const* d_in, const int* in_sizes, int n_in,
                              void* d_out, int out_size) {
    (void)in_sizes; (void)n_in; (void)out_size;
    const float* obs = (const float*)d_in[0];
    const float* eW0 = (const float*)d_in[1];
    const float* eb0 = (const float*)d_in[2];
    const float* eW1 = (const float*)d_in[3];
    const float* eb1 = (const float*)d_in[4];
    const float* eW2 = (const float*)d_in[5];
    const float* eb2 = (const float*)d_in[6];
    const float* dW0 = (const float*)d_in[7];
    const float* db0 = (const float*)d_in[8];
    const float* dW1 = (const float*)d_in[9];
    const float* db1 = (const float*)d_in[10];
    const float* dW2 = (const float*)d_in[11];
    const float* db2 = (const float*)d_in[12];
    const float* cb  = (const float*)d_in[13];
    float* out = (float*)d_out;

    cudaFuncSetAttribute(pwl_build_kernel,
                         cudaFuncAttributeMaxDynamicSharedMemorySize, P_SMEM_BYTES);
    cudaFuncSetAttribute(enc_emb_kernel,
                         cudaFuncAttributeMaxDynamicSharedMemorySize, E1_SMEM_BYTES);
    cudaFuncSetAttribute(dec_kernel,
                         cudaFuncAttributeMaxDynamicSharedMemorySize, D_SMEM_BYTES);

    pwl_build_kernel<<<OBSD * 4, 256, P_SMEM_BYTES>>>(eW0, eb0, eW1, eb1);
    enc_emb_kernel<<<ROWS / 128, 512, E1_SMEM_BYTES>>>(obs, eW2, eb2);
    enc_dist_kernel<<<ROWS / E2_ROWS, 256>>>(cb);
    dec_kernel<<<BATCH / DTR, DTHREADS, D_SMEM_BYTES>>>(
        dW0, db0, dW1, db1, dW2, db2, out);
}